// round 1
// baseline (speedup 1.0000x reference)
#include <cuda_runtime.h>

// Fixed problem shapes
#define B_ 16
#define T_ 8
#define C_ 2048
#define H_ 16
#define D_ 128
#define MAXSEQ 4096
#define STARTPOS 4088
#define S_ 4096          // STARTPOS + T_
#define QKV_STRIDE (3*C_)

// Scratch (static device globals: allocation-free)
__device__ float g_qkv[B_*T_*3*C_];   // 128 x 6144
__device__ float g_att[B_*T_*C_];     // 128 x 2048

typedef unsigned long long u64;

__device__ __forceinline__ u64 dupf(float x) {
    u64 r; unsigned xi = __float_as_uint(x);
    asm("mov.b64 %0, {%1, %1};" : "=l"(r) : "r"(xi));
    return r;
}
__device__ __forceinline__ void fma2(u64& d, u64 a, u64 b) {
    asm("fma.rn.f32x2 %0, %1, %2, %0;" : "+l"(d) : "l"(a), "l"(b));
}
__device__ __forceinline__ float2 unpk(u64 v) {
    unsigned lo, hi;
    asm("mov.b64 {%0, %1}, %2;" : "=r"(lo), "=r"(hi) : "l"(v));
    return make_float2(__uint_as_float(lo), __uint_as_float(hi));
}
__device__ __forceinline__ float hsum2(u64 v) {
    float2 f = unpk(v);
    return f.x + f.y;
}

// ---------------------------------------------------------------------------
// GEMM: C[M,N] = A[M,K] @ B[K,N] + bias[N]    (all row-major, fp32)
// BM=32, BN=64, BK=16, 128 threads, 4x4 micro-tile via f32x2 pairs along M.
// ---------------------------------------------------------------------------
__global__ __launch_bounds__(128) void gemm_bias_kernel(
    const float* __restrict__ A, const float* __restrict__ Bw,
    const float* __restrict__ bias, float* __restrict__ Cc,
    int M, int N, int K)
{
    constexpr int BM = 32, BN = 64, BK = 16;
    __shared__ float As[BK][BM];   // transposed A tile
    __shared__ float Bs[BK][BN];

    const int tid = threadIdx.x;
    const int tx = tid & 15;       // 0..15 -> N
    const int ty = tid >> 4;       // 0..7  -> M
    const int m0 = blockIdx.y * BM;
    const int n0 = blockIdx.x * BN;

    // A-tile load mapping: 32 rows x 16 cols = 128 float4
    const int ar  = tid >> 2;      // 0..31
    const int ac4 = tid & 3;       // 0..3
    // B-tile load mapping: 16 rows x 64 cols = 256 float4 (2 per thread)
    const int br  = tid >> 4;      // 0..7
    const int bc4 = tid & 15;      // 0..15

    u64 acc[2][4];
    #pragma unroll
    for (int i = 0; i < 2; i++)
        #pragma unroll
        for (int n = 0; n < 4; n++) acc[i][n] = 0ull;

    for (int k0 = 0; k0 < K; k0 += BK) {
        float4 av = *(const float4*)(A + (size_t)(m0 + ar)*K + k0 + ac4*4);
        As[ac4*4+0][ar] = av.x;
        As[ac4*4+1][ar] = av.y;
        As[ac4*4+2][ar] = av.z;
        As[ac4*4+3][ar] = av.w;
        float4 bv0 = *(const float4*)(Bw + (size_t)(k0 + br    )*N + n0 + bc4*4);
        float4 bv1 = *(const float4*)(Bw + (size_t)(k0 + br + 8)*N + n0 + bc4*4);
        *(float4*)&Bs[br    ][bc4*4] = bv0;
        *(float4*)&Bs[br + 8][bc4*4] = bv1;
        __syncthreads();

        #pragma unroll
        for (int kk = 0; kk < BK; kk++) {
            ulonglong2 a2 = *(const ulonglong2*)&As[kk][ty*4];  // rows (ty*4..ty*4+3) as 2 pairs
            float4 b4 = *(const float4*)&Bs[kk][tx*4];
            u64 bd;
            bd = dupf(b4.x); fma2(acc[0][0], a2.x, bd); fma2(acc[1][0], a2.y, bd);
            bd = dupf(b4.y); fma2(acc[0][1], a2.x, bd); fma2(acc[1][1], a2.y, bd);
            bd = dupf(b4.z); fma2(acc[0][2], a2.x, bd); fma2(acc[1][2], a2.y, bd);
            bd = dupf(b4.w); fma2(acc[0][3], a2.x, bd); fma2(acc[1][3], a2.y, bd);
        }
        __syncthreads();
    }

    float4 bia = *(const float4*)(bias + n0 + tx*4);
    #pragma unroll
    for (int i = 0; i < 2; i++) {
        float2 u0 = unpk(acc[i][0]);
        float2 u1 = unpk(acc[i][1]);
        float2 u2 = unpk(acc[i][2]);
        float2 u3 = unpk(acc[i][3]);
        float4 lo = make_float4(u0.x + bia.x, u1.x + bia.y, u2.x + bia.z, u3.x + bia.w);
        float4 hi = make_float4(u0.y + bia.x, u1.y + bia.y, u2.y + bia.z, u3.y + bia.w);
        size_t rlo = (size_t)(m0 + ty*4 + 2*i);
        *(float4*)(Cc + rlo*N + n0 + tx*4)       = lo;
        *(float4*)(Cc + (rlo + 1)*N + n0 + tx*4) = hi;
    }
}

// ---------------------------------------------------------------------------
// Attention: one block per (b,h). 256 threads (8 warps).
// smem: q[8][128] | scores2[4096][8] (reused as ypart[8w][8j][128]) | smax[8] | ssum[8]
// ---------------------------------------------------------------------------
#define SMEM_FLOATS (T_*D_ + S_*T_ + 16)
#define SMEM_BYTES  (SMEM_FLOATS * 4)

__global__ __launch_bounds__(256) void attn_kernel(
    const float* __restrict__ k_cache,
    const float* __restrict__ v_cache,
    const float* __restrict__ qkv,
    float* __restrict__ att_out)
{
    extern __shared__ float sm[];
    float* qs   = sm;                 // 1024 floats
    float* sc   = sm + T_*D_;         // 32768 floats: [s][j]
    float* smax = sc + S_*T_;         // 8
    float* ssum = smax + T_;          // 8

    const int tid  = threadIdx.x;
    const int bh   = blockIdx.x;
    const int b    = bh / H_;
    const int h    = bh % H_;
    const int w    = tid >> 5;
    const int lane = tid & 31;

    // ---- load q[8][128] into smem, zero ssum ----
    {
        int j  = tid >> 5;           // 8 rows, 32 float4 each -> f = tid covers all 256
        int d4 = tid & 31;
        float4 qv = *(const float4*)(qkv + (size_t)(b*T_ + j)*QKV_STRIDE + h*D_ + d4*4);
        *(float4*)&qs[j*D_ + d4*4] = qv;
        if (tid < T_) ssum[tid] = 0.f;
    }
    __syncthreads();

    // ---- pass 1: scores[s][j] = (q_j . k_s) * scale ----
    const float scale = 0.08838834764831845f;   // 1/sqrt(128)
    const ulonglong2* q2 = (const ulonglong2*)qs;
    #pragma unroll 1
    for (int i = 0; i < 4; i++) {
        int sbase = tid + i*1024;
        const ulonglong2* kp[4];
        #pragma unroll
        for (int c = 0; c < 4; c++) {
            int s = sbase + c*256;
            const float* base = (s >= STARTPOS)
                ? qkv + (size_t)(b*T_ + (s - STARTPOS))*QKV_STRIDE + C_ + h*D_
                : k_cache + ((size_t)(b*H_ + h)*MAXSEQ + s)*(size_t)D_;
            kp[c] = (const ulonglong2*)base;
        }
        u64 acc[4][8];
        #pragma unroll
        for (int c = 0; c < 4; c++)
            #pragma unroll
            for (int j = 0; j < 8; j++) acc[c][j] = 0ull;

        #pragma unroll 4
        for (int d4 = 0; d4 < 32; d4++) {
            ulonglong2 kv0 = kp[0][d4];
            ulonglong2 kv1 = kp[1][d4];
            ulonglong2 kv2 = kp[2][d4];
            ulonglong2 kv3 = kp[3][d4];
            #pragma unroll
            for (int j = 0; j < 8; j++) {
                ulonglong2 qv = q2[j*32 + d4];   // broadcast LDS.128
                fma2(acc[0][j], kv0.x, qv.x); fma2(acc[0][j], kv0.y, qv.y);
                fma2(acc[1][j], kv1.x, qv.x); fma2(acc[1][j], kv1.y, qv.y);
                fma2(acc[2][j], kv2.x, qv.x); fma2(acc[2][j], kv2.y, qv.y);
                fma2(acc[3][j], kv3.x, qv.x); fma2(acc[3][j], kv3.y, qv.y);
            }
        }
        #pragma unroll
        for (int c = 0; c < 4; c++) {
            int s = sbase + c*256;
            float4 r0 = make_float4(hsum2(acc[c][0])*scale, hsum2(acc[c][1])*scale,
                                    hsum2(acc[c][2])*scale, hsum2(acc[c][3])*scale);
            float4 r1 = make_float4(hsum2(acc[c][4])*scale, hsum2(acc[c][5])*scale,
                                    hsum2(acc[c][6])*scale, hsum2(acc[c][7])*scale);
            *(float4*)&sc[s*8]     = r0;
            *(float4*)&sc[s*8 + 4] = r1;
        }
    }
    __syncthreads();

    // ---- softmax: max (warp j), then exp + rowsum ----
    {
        int j = w;   // warp w handles row j
        float m = -3.4e38f;
        for (int s = lane; s < S_; s += 32) m = fmaxf(m, sc[s*8 + j]);
        #pragma unroll
        for (int o = 16; o; o >>= 1) m = fmaxf(m, __shfl_xor_sync(0xffffffffu, m, o));
        if (lane == 0) smax[j] = m;
    }
    __syncthreads();
    {
        int jg = (tid & 1) * 4;
        float m0 = smax[jg], m1 = smax[jg+1], m2 = smax[jg+2], m3 = smax[jg+3];
        float a0 = 0.f, a1 = 0.f, a2 = 0.f, a3 = 0.f;
        float4* sc4 = (float4*)sc;
        for (int f = tid; f < S_*2; f += 256) {
            float4 v = sc4[f];
            v.x = __expf(v.x - m0);
            v.y = __expf(v.y - m1);
            v.z = __expf(v.z - m2);
            v.w = __expf(v.w - m3);
            sc4[f] = v;
            a0 += v.x; a1 += v.y; a2 += v.z; a3 += v.w;
        }
        atomicAdd(&ssum[jg],   a0);
        atomicAdd(&ssum[jg+1], a1);
        atomicAdd(&ssum[jg+2], a2);
        atomicAdd(&ssum[jg+3], a3);
    }
    __syncthreads();

    // ---- pass 2: out[j][d] = sum_s p[j][s] * v[s][d]; warp w covers its s-octave ----
    u64 acc[8][2];
    #pragma unroll
    for (int j = 0; j < 8; j++) { acc[j][0] = 0ull; acc[j][1] = 0ull; }
    const int db = lane * 4;
    const int s0 = w * (S_ / 8);
    #pragma unroll 2
    for (int s = s0; s < s0 + S_/8; s++) {
        const float* vrow = (s >= STARTPOS)
            ? qkv + (size_t)(b*T_ + (s - STARTPOS))*QKV_STRIDE + 2*C_ + h*D_
            : v_cache + ((size_t)(b*H_ + h)*MAXSEQ + s)*(size_t)D_;
        ulonglong2 vv = *(const ulonglong2*)(vrow + db);
        float4 p0 = *(const float4*)&sc[s*8];
        float4 p1 = *(const float4*)&sc[s*8 + 4];
        float pj[8] = {p0.x, p0.y, p0.z, p0.w, p1.x, p1.y, p1.z, p1.w};
        #pragma unroll
        for (int j = 0; j < 8; j++) {
            u64 pd = dupf(pj[j]);
            fma2(acc[j][0], vv.x, pd);
            fma2(acc[j][1], vv.y, pd);
        }
    }
    __syncthreads();   // all warps done reading sc
    #pragma unroll
    for (int j = 0; j < 8; j++) {
        ulonglong2 st; st.x = acc[j][0]; st.y = acc[j][1];
        *(ulonglong2*)&sc[w*1024 + j*128 + db] = st;    // ypart[w][j][d]
    }
    __syncthreads();
    for (int f = tid; f < 1024; f += 256) {
        float sum = 0.f;
        #pragma unroll
        for (int ww = 0; ww < 8; ww++) sum += sc[ww*1024 + f];
        int j = f >> 7, d = f & 127;
        att_out[(size_t)(b*T_ + j)*C_ + h*D_ + d] = sum / ssum[j];
    }
}

// ---------------------------------------------------------------------------
extern "C" void kernel_launch(void* const* d_in, const int* in_sizes, int n_in,
                              void* d_out, int out_size)
{
    const float* x  = (const float*)d_in[0];
    const float* kc = (const float*)d_in[1];
    const float* vc = (const float*)d_in[2];
    const float* wa = (const float*)d_in[3];
    const float* ba = (const float*)d_in[4];
    const float* wp = (const float*)d_in[5];
    const float* bp = (const float*)d_in[6];
    float* out = (float*)d_out;

    float *qkv, *att;
    cudaGetSymbolAddress((void**)&qkv, g_qkv);
    cudaGetSymbolAddress((void**)&att, g_att);

    cudaFuncSetAttribute(attn_kernel,
                         cudaFuncAttributeMaxDynamicSharedMemorySize, SMEM_BYTES);

    // 1) QKV projection: [128,2048] @ [2048,6144]
    gemm_bias_kernel<<<dim3(3*C_/64, (B_*T_)/32), 128>>>(x, wa, ba, qkv,
                                                         B_*T_, 3*C_, C_);
    // 2) Attention: 256 blocks (one per b,h)
    attn_kernel<<<B_*H_, 256, SMEM_BYTES>>>(kc, vc, qkv, att);
    // 3) Output projection: [128,2048] @ [2048,2048] -> d_out
    gemm_bias_kernel<<<dim3(C_/64, (B_*T_)/32), 128>>>(att, wp, bp, out,
                                                       B_*T_, C_, C_);
}

// round 6
// speedup vs baseline: 1.3449x; 1.3449x over previous
#include <cuda_runtime.h>

// Fixed problem shapes
#define B_ 16
#define T_ 8
#define C_ 2048
#define H_ 16
#define D_ 128
#define MAXSEQ 4096
#define STARTPOS 4088
#define S_ 4096
#define QKV_STRIDE (3*C_)
#define M_ (B_*T_)          // 128

// Scratch (static device globals: allocation-free)
__device__ float g_xT  [C_*M_];            // x transposed [2048][128]
__device__ float g_qkv [M_*3*C_];          // [128][6144]
__device__ float g_qkvp[2*M_*3*C_];        // split-K partials (2)
__device__ float g_attT[C_*M_];            // attention out transposed [2048][128]
__device__ float g_outp[8*M_*C_];          // proj split-K partials (8)
__device__ float g_sc  [(size_t)B_*H_*S_*T_];  // scores [bh][s][8]

typedef unsigned long long u64;

__device__ __forceinline__ u64 dupf(float x) {
    u64 r; unsigned xi = __float_as_uint(x);
    asm("mov.b64 %0, {%1, %1};" : "=l"(r) : "r"(xi));
    return r;
}
__device__ __forceinline__ void fma2(u64& d, u64 a, u64 b) {
    asm("fma.rn.f32x2 %0, %1, %2, %0;" : "+l"(d) : "l"(a), "l"(b));
}
__device__ __forceinline__ float2 unpk(u64 v) {
    unsigned lo, hi;
    asm("mov.b64 {%0, %1}, %2;" : "=r"(lo), "=r"(hi) : "l"(v));
    return make_float2(__uint_as_float(lo), __uint_as_float(hi));
}
__device__ __forceinline__ float hsum2(u64 v) { float2 f = unpk(v); return f.x + f.y; }

__device__ __forceinline__ void cp16(unsigned dst, const void* src) {
    asm volatile("cp.async.cg.shared.global [%0], [%1], 16;\n" :: "r"(dst), "l"(src));
}
#define CP_COMMIT()  asm volatile("cp.async.commit_group;\n" ::: "memory")
#define CP_WAIT(n)   asm volatile("cp.async.wait_group %0;\n" :: "n"(n) : "memory")

// ---------------------------------------------------------------------------
// transpose x[128][2048] -> xT[2048][128]
// ---------------------------------------------------------------------------
__global__ __launch_bounds__(256) void transpose_kernel(const float* __restrict__ x,
                                                        float* __restrict__ xT) {
    int idx = blockIdx.x * 256 + threadIdx.x;          // 262144 total
    int r = idx >> 11;          // bt
    int c = idx & 2047;         // channel
    xT[c * M_ + r] = x[idx];
}

// ---------------------------------------------------------------------------
// GEMM: C[128][N] = AT^T[128][2048] @ B[2048][N] + bias, split-K (KS slices).
// AT is [2048][128] (K-major). grid = (N/128, KS), 256 threads.
// slice 0 -> C (+bias); slice s>0 -> P[(s-1)][128][N].
// ---------------------------------------------------------------------------
__global__ __launch_bounds__(256) void gemm_splitk_kernel(
    const float* __restrict__ AT, const float* __restrict__ Bw,
    const float* __restrict__ bias, float* __restrict__ Cc,
    float* __restrict__ Pp, int N, int KS)
{
    __shared__ float As[2][8][128];
    __shared__ float Bs[2][8][128];

    const int tid = threadIdx.x;
    const int tx = tid & 15;
    const int ty = tid >> 4;
    const int n0 = blockIdx.x * 128;
    const int slice = blockIdx.y;

    const int KBTOT = 256;                // 2048/8
    const int kb0 = (slice * KBTOT) / KS;
    const int kb1 = ((slice + 1) * KBTOT) / KS;

    // load mapping: chunk m = tid -> r = m>>5 (kk-row), c = m&31 (16B col chunk)
    const int lr = tid >> 5;
    const int lc = tid & 31;
    unsigned sA = (unsigned)__cvta_generic_to_shared(&As[0][0][0]);
    unsigned sB = (unsigned)__cvta_generic_to_shared(&Bs[0][0][0]);

    u64 acc[4][8];
    #pragma unroll
    for (int p = 0; p < 4; p++)
        #pragma unroll
        for (int n = 0; n < 8; n++) acc[p][n] = 0ull;

    // prologue load
    {
        int k = kb0 * 8 + lr;
        cp16(sA + (unsigned)(lr * 128 + lc * 4) * 4u, AT + (size_t)k * M_ + lc * 4);
        cp16(sB + (unsigned)(lr * 128 + lc * 4) * 4u, Bw + (size_t)k * N + n0 + lc * 4);
        CP_COMMIT();
    }

    for (int kb = kb0; kb < kb1; kb++) {
        int buf = (kb - kb0) & 1;
        if (kb + 1 < kb1) {
            int nb = buf ^ 1;
            int k = (kb + 1) * 8 + lr;
            cp16(sA + (unsigned)(nb * 1024 + lr * 128 + lc * 4) * 4u, AT + (size_t)k * M_ + lc * 4);
            cp16(sB + (unsigned)(nb * 1024 + lr * 128 + lc * 4) * 4u, Bw + (size_t)k * N + n0 + lc * 4);
            CP_COMMIT();
            CP_WAIT(1);
        } else {
            CP_WAIT(0);
        }
        __syncthreads();

        #pragma unroll
        for (int kk = 0; kk < 8; kk++) {
            ulonglong2 a0 = *(const ulonglong2*)&As[buf][kk][ty * 4];
            ulonglong2 a1 = *(const ulonglong2*)&As[buf][kk][64 + ty * 4];
            float4 b0 = *(const float4*)&Bs[buf][kk][tx * 4];
            float4 b1 = *(const float4*)&Bs[buf][kk][64 + tx * 4];
            u64 bd[8];
            bd[0] = dupf(b0.x); bd[1] = dupf(b0.y); bd[2] = dupf(b0.z); bd[3] = dupf(b0.w);
            bd[4] = dupf(b1.x); bd[5] = dupf(b1.y); bd[6] = dupf(b1.z); bd[7] = dupf(b1.w);
            #pragma unroll
            for (int n = 0; n < 8; n++) {
                fma2(acc[0][n], a0.x, bd[n]);
                fma2(acc[1][n], a0.y, bd[n]);
                fma2(acc[2][n], a1.x, bd[n]);
                fma2(acc[3][n], a1.y, bd[n]);
            }
        }
        __syncthreads();
    }

    // epilogue
    float* dst = (slice == 0) ? Cc : Pp + (size_t)(slice - 1) * M_ * N;
    float4 bi0 = make_float4(0.f, 0.f, 0.f, 0.f), bi1 = bi0;
    if (slice == 0) {
        bi0 = *(const float4*)(bias + n0 + tx * 4);
        bi1 = *(const float4*)(bias + n0 + 64 + tx * 4);
    }
    #pragma unroll
    for (int p = 0; p < 4; p++) {
        int mr = (p < 2) ? (ty * 4 + 2 * p) : (64 + ty * 4 + 2 * (p - 2));
        float2 u0 = unpk(acc[p][0]), u1 = unpk(acc[p][1]), u2 = unpk(acc[p][2]), u3 = unpk(acc[p][3]);
        float2 u4 = unpk(acc[p][4]), u5 = unpk(acc[p][5]), u6 = unpk(acc[p][6]), u7 = unpk(acc[p][7]);
        float4 lo0 = make_float4(u0.x + bi0.x, u1.x + bi0.y, u2.x + bi0.z, u3.x + bi0.w);
        float4 hi0 = make_float4(u0.y + bi0.x, u1.y + bi0.y, u2.y + bi0.z, u3.y + bi0.w);
        float4 lo1 = make_float4(u4.x + bi1.x, u5.x + bi1.y, u6.x + bi1.z, u7.x + bi1.w);
        float4 hi1 = make_float4(u4.y + bi1.x, u5.y + bi1.y, u6.y + bi1.z, u7.y + bi1.w);
        *(float4*)(dst + (size_t)mr * N + n0 + tx * 4)            = lo0;
        *(float4*)(dst + (size_t)(mr + 1) * N + n0 + tx * 4)      = hi0;
        *(float4*)(dst + (size_t)mr * N + n0 + 64 + tx * 4)       = lo1;
        *(float4*)(dst + (size_t)(mr + 1) * N + n0 + 64 + tx * 4) = hi1;
    }
}

// dst[i] += sum_p parts[p][i]   (float4 granularity)
__global__ __launch_bounds__(256) void addparts_kernel(float* __restrict__ dst,
                                                       const float* __restrict__ parts,
                                                       int nparts, int n4) {
    int i = blockIdx.x * 256 + threadIdx.x;
    if (i >= n4) return;
    float4 v = ((float4*)dst)[i];
    for (int p = 0; p < nparts; p++) {
        float4 a = ((const float4*)parts)[(size_t)p * n4 + i];
        v.x += a.x; v.y += a.y; v.z += a.z; v.w += a.w;
    }
    ((float4*)dst)[i] = v;
}

// ---------------------------------------------------------------------------
// Attention: one block per (b,h), 512 threads.
// Phase A: scores -> g_sc (K staged via cp.async, XOR-swizzled smem)
// Phase B: softmax (max, exp-in-place, sums)
// Phase C: PV (direct coalesced V loads) -> g_attT (transposed for proj GEMM)
// ---------------------------------------------------------------------------
#define TILE_OFF 0                 // 2 x 128 x 128 floats = 32768
#define QS_OFF   32768             // 1024
#define PP_OFF   33792             // 4*128*9 = 4608
#define WMAX_OFF 38400             // 128
#define SMAX_OFF 38528             // 8
#define WSUM_OFF 38536             // 128
#define SSUM_OFF 38664             // 8
#define ATT_SMEM_FLOATS 38672
#define ATT_SMEM_BYTES  (ATT_SMEM_FLOATS*4)

__device__ __forceinline__ int swiz(int r, int c) {       // 16B-chunk swizzle in a 512B row
    return (c & 24) | ((c & 7) ^ (r & 7));
}

__global__ __launch_bounds__(512) void attn_kernel(
    const float* __restrict__ k_cache,
    const float* __restrict__ v_cache,
    const float* __restrict__ qkv,
    float* __restrict__ attT)
{
    extern __shared__ float sm[];
    const int tid  = threadIdx.x;
    const int bh   = blockIdx.x;
    const int b    = bh >> 4;
    const int h    = bh & 15;
    const int w    = tid >> 5;
    const int lane = tid & 31;

    float* tile = sm + TILE_OFF;
    float* qs   = sm + QS_OFF;
    float* pp   = sm + PP_OFF;
    float* scb  = g_sc + (size_t)bh * S_ * 8;

    unsigned tile_s = (unsigned)__cvta_generic_to_shared(tile);

    // load q (scaled)
    const float scale = 0.08838834764831845f;   // 1/sqrt(128)
    #pragma unroll
    for (int f = tid; f < T_ * D_; f += 512) {
        int j = f >> 7, d = f & 127;
        qs[f] = qkv[(size_t)(b * T_ + j) * QKV_STRIDE + h * D_ + d] * scale;
    }
    __syncthreads();

    // ---------------- Phase A ----------------
    const int r_ = tid & 127;       // row within tile
    const int q4 = tid >> 7;        // quarter of d (32 floats)

    // tile loader: 4096 16B chunks per tile, thread does 8
    auto load_tile = [&](int t, int buf) {
        int s0 = t * 128;
        #pragma unroll
        for (int i = 0; i < 8; i++) {
            int m = tid + 512 * i;
            int rr = m >> 5, cc = m & 31;
            int s = s0 + rr;
            const float* src = (s >= STARTPOS)
                ? qkv + (size_t)(b * T_ + (s - STARTPOS)) * QKV_STRIDE + C_ + h * D_ + cc * 4
                : k_cache + ((size_t)(b * H_ + h) * MAXSEQ + s) * (size_t)D_ + cc * 4;
            // chunk index: buf*4096 (16KB-chunks per buffer) + row*32 + swizzled col
            unsigned dst = tile_s + ((unsigned)buf * 4096u + (unsigned)(rr * 32 + swiz(rr, cc))) * 16u;
            cp16(dst, src);
        }
        CP_COMMIT();
    };

    load_tile(0, 0);
    for (int t = 0; t < 32; t++) {
        int buf = t & 1;
        if (t + 1 < 32) { load_tile(t + 1, buf ^ 1); CP_WAIT(1); }
        else            { CP_WAIT(0); }
        __syncthreads();

        // compute partial dots: thread (r_, q4) over 32 d-floats
        u64 acc[8];
        #pragma unroll
        for (int j = 0; j < 8; j++) acc[j] = 0ull;
        const float* tb = tile + buf * 16384;
        #pragma unroll
        for (int i = 0; i < 8; i++) {
            int c = q4 * 8 + i;
            ulonglong2 kk2 = *(const ulonglong2*)(tb + (r_ * 32 + swiz(r_, c)) * 4);
            int d0 = c * 4;
            #pragma unroll
            for (int j = 0; j < 8; j++) {
                ulonglong2 q2 = *(const ulonglong2*)(qs + j * 128 + d0);
                fma2(acc[j], kk2.x, q2.x);
                fma2(acc[j], kk2.y, q2.y);
            }
        }
        #pragma unroll
        for (int j = 0; j < 8; j++) pp[(q4 * 128 + r_) * 9 + j] = hsum2(acc[j]);
        __syncthreads();

        // combine quarters + store scores (coalesced 32B/row)
        if (tid < 128) {
            int r = tid;
            float v[8];
            #pragma unroll
            for (int j = 0; j < 8; j++)
                v[j] = pp[r * 9 + j] + pp[(128 + r) * 9 + j]
                     + pp[(256 + r) * 9 + j] + pp[(384 + r) * 9 + j];
            float* dst = scb + (size_t)(t * 128 + r) * 8;
            *(float4*)dst       = make_float4(v[0], v[1], v[2], v[3]);
            *(float4*)(dst + 4) = make_float4(v[4], v[5], v[6], v[7]);
        }
    }
    __syncthreads();

    // ---------------- Phase B: softmax ----------------
    float* wmax = sm + WMAX_OFF;
    float* smax = sm + SMAX_OFF;
    float* wsum = sm + WSUM_OFF;
    float* ssum = sm + SSUM_OFF;
    {
        float mx[8];
        #pragma unroll
        for (int j = 0; j < 8; j++) mx[j] = -3.4e38f;
        for (int s = tid; s < S_; s += 512) {
            float4 a = *(const float4*)(scb + (size_t)s * 8);
            float4 c = *(const float4*)(scb + (size_t)s * 8 + 4);
            mx[0] = fmaxf(mx[0], a.x); mx[1] = fmaxf(mx[1], a.y);
            mx[2] = fmaxf(mx[2], a.z); mx[3] = fmaxf(mx[3], a.w);
            mx[4] = fmaxf(mx[4], c.x); mx[5] = fmaxf(mx[5], c.y);
            mx[6] = fmaxf(mx[6], c.z); mx[7] = fmaxf(mx[7], c.w);
        }
        #pragma unroll
        for (int o = 16; o; o >>= 1)
            #pragma unroll
            for (int j = 0; j < 8; j++) mx[j] = fmaxf(mx[j], __shfl_xor_sync(~0u, mx[j], o));
        if (lane == 0)
            #pragma unroll
            for (int j = 0; j < 8; j++) wmax[w * 8 + j] = mx[j];
    }
    __syncthreads();
    if (tid < 8) {
        float m = wmax[tid];
        for (int ww = 1; ww < 16; ww++) m = fmaxf(m, wmax[ww * 8 + tid]);
        smax[tid] = m;
    }
    __syncthreads();
    {
        float m[8], sum[8];
        #pragma unroll
        for (int j = 0; j < 8; j++) { m[j] = smax[j]; sum[j] = 0.f; }
        for (int s = tid; s < S_; s += 512) {
            float4 a = *(const float4*)(scb + (size_t)s * 8);
            float4 c = *(const float4*)(scb + (size_t)s * 8 + 4);
            a.x = __expf(a.x - m[0]); a.y = __expf(a.y - m[1]);
            a.z = __expf(a.z - m[2]); a.w = __expf(a.w - m[3]);
            c.x = __expf(c.x - m[4]); c.y = __expf(c.y - m[5]);
            c.z = __expf(c.z - m[6]); c.w = __expf(c.w - m[7]);
            *(float4*)(scb + (size_t)s * 8)     = a;
            *(float4*)(scb + (size_t)s * 8 + 4) = c;
            sum[0] += a.x; sum[1] += a.y; sum[2] += a.z; sum[3] += a.w;
            sum[4] += c.x; sum[5] += c.y; sum[6] += c.z; sum[7] += c.w;
        }
        #pragma unroll
        for (int o = 16; o; o >>= 1)
            #pragma unroll
            for (int j = 0; j < 8; j++) sum[j] += __shfl_xor_sync(~0u, sum[j], o);
        if (lane == 0)
            #pragma unroll
            for (int j = 0; j < 8; j++) wsum[w * 8 + j] = sum[j];
    }
    __syncthreads();
    if (tid < 8) {
        float s = 0.f;
        for (int ww = 0; ww < 16; ww++) s += wsum[ww * 8 + tid];
        ssum[tid] = s;
    }
    __syncthreads();

    // ---------------- Phase C: PV ----------------
    u64 acc[8][2];
    #pragma unroll
    for (int j = 0; j < 8; j++) { acc[j][0] = 0ull; acc[j][1] = 0ull; }
    const int db = lane * 4;
    const int sbeg = w * 256;
    for (int s = sbeg; s < sbeg + 256; s += 4) {
        #pragma unroll
        for (int u = 0; u < 4; u++) {
            int ss = s + u;
            const float* vrow = (ss >= STARTPOS)
                ? qkv + (size_t)(b * T_ + (ss - STARTPOS)) * QKV_STRIDE + 2 * C_ + h * D_
                : v_cache + ((size_t)(b * H_ + h) * MAXSEQ + ss) * (size_t)D_;
            ulonglong2 vv = *(const ulonglong2*)(vrow + db);
            float4 p0 = *(const float4*)(scb + (size_t)ss * 8);
            float4 p1 = *(const float4*)(scb + (size_t)ss * 8 + 4);
            float pj[8] = {p0.x, p0.y, p0.z, p0.w, p1.x, p1.y, p1.z, p1.w};
            #pragma unroll
            for (int j = 0; j < 8; j++) {
                u64 pd = dupf(pj[j]);
                fma2(acc[j][0], vv.x, pd);
                fma2(acc[j][1], vv.y, pd);
            }
        }
    }
    __syncthreads();   // tile buffer reuse safe
    float* ypart = tile;   // [16][1024]
    #pragma unroll
    for (int j = 0; j < 8; j++) {
        ulonglong2 st; st.x = acc[j][0]; st.y = acc[j][1];
        *(ulonglong2*)&ypart[w * 1024 + j * 128 + db] = st;
    }
    __syncthreads();
    #pragma unroll
    for (int f = tid; f < 1024; f += 512) {
        float sum = 0.f;
        #pragma unroll
        for (int ww = 0; ww < 16; ww++) sum += ypart[ww * 1024 + f];
        int j = f >> 7, d = f & 127;
        attT[(size_t)(h * D_ + d) * M_ + b * T_ + j] = sum / ssum[j];
    }
}

// ---------------------------------------------------------------------------
extern "C" void kernel_launch(void* const* d_in, const int* in_sizes, int n_in,
                              void* d_out, int out_size)
{
    const float* x  = (const float*)d_in[0];
    const float* kc = (const float*)d_in[1];
    const float* vc = (const float*)d_in[2];
    const float* wa = (const float*)d_in[3];
    const float* ba = (const float*)d_in[4];
    const float* wp = (const float*)d_in[5];
    const float* bp = (const float*)d_in[6];
    float* out = (float*)d_out;

    float *xT, *qkv, *qkvp, *attT, *outp;
    cudaGetSymbolAddress((void**)&xT,   g_xT);
    cudaGetSymbolAddress((void**)&qkv,  g_qkv);
    cudaGetSymbolAddress((void**)&qkvp, g_qkvp);
    cudaGetSymbolAddress((void**)&attT, g_attT);
    cudaGetSymbolAddress((void**)&outp, g_outp);

    cudaFuncSetAttribute(attn_kernel,
                         cudaFuncAttributeMaxDynamicSharedMemorySize, ATT_SMEM_BYTES);

    // 1) transpose x -> xT
    transpose_kernel<<<(M_*C_)/256, 256>>>(x, xT);
    // 2) QKV GEMM, split-K 3 (48x3 = 144 blocks)
    gemm_splitk_kernel<<<dim3(3*C_/128, 3), 256>>>(xT, wa, ba, qkv, qkvp, 3*C_, 3);
    // 3) reduce partials into qkv
    addparts_kernel<<<(M_*3*C_/4 + 255)/256, 256>>>(qkv, qkvp, 2, M_*3*C_/4);
    // 4) attention -> attT
    attn_kernel<<<B_*H_, 512, ATT_SMEM_BYTES>>>(kc, vc, qkv, attT);
    // 5) proj GEMM, split-K 9 (16x9 = 144 blocks)
    gemm_splitk_kernel<<<dim3(C_/128, 9), 256>>>(attT, wp, bp, out, outp, C_, 9);
    // 6) reduce partials into out
    addparts_kernel<<<(M_*C_/4 + 255)/256, 256>>>(out, outp, 8, M_*C_/4);
}

// round 7
// speedup vs baseline: 2.1329x; 1.5859x over previous
#include <cuda_runtime.h>

// Fixed problem shapes
#define B_ 16
#define T_ 8
#define C_ 2048
#define H_ 16
#define D_ 128
#define MAXSEQ 4096
#define STARTPOS 4088
#define S_ 4096
#define QKV_STRIDE (3*C_)
#define M_ (B_*T_)          // 128
#define CH_ 512             // attention s-chunk
#define NCH 8               // S_/CH_

// Scratch (static device globals: allocation-free)
__device__ float g_xT  [C_*M_];            // x transposed [2048][128]
__device__ float g_qkv [M_*3*C_];          // [128][6144]
__device__ float g_qkvp[2*M_*3*C_];        // split-K partials (2)
__device__ float g_attT[C_*M_];            // attention out transposed [2048][128]
__device__ float g_outp[8*M_*C_];          // proj split-K partials (8)
__device__ float g_py  [(size_t)B_*H_*NCH*T_*D_];  // PV partials [2048][1024] (8MB)
__device__ float g_pm  [B_*H_*NCH*T_];     // chunk maxes
__device__ float g_pl  [B_*H_*NCH*T_];     // chunk sums

typedef unsigned long long u64;

__device__ __forceinline__ u64 dupf(float x) {
    u64 r; unsigned xi = __float_as_uint(x);
    asm("mov.b64 %0, {%1, %1};" : "=l"(r) : "r"(xi));
    return r;
}
__device__ __forceinline__ void fma2(u64& d, u64 a, u64 b) {
    asm("fma.rn.f32x2 %0, %1, %2, %0;" : "+l"(d) : "l"(a), "l"(b));
}
__device__ __forceinline__ float2 unpk(u64 v) {
    unsigned lo, hi;
    asm("mov.b64 {%0, %1}, %2;" : "=r"(lo), "=r"(hi) : "l"(v));
    return make_float2(__uint_as_float(lo), __uint_as_float(hi));
}
__device__ __forceinline__ float hsum2(u64 v) { float2 f = unpk(v); return f.x + f.y; }

__device__ __forceinline__ void cp16(unsigned dst, const void* src) {
    asm volatile("cp.async.cg.shared.global [%0], [%1], 16;\n" :: "r"(dst), "l"(src));
}
#define CP_COMMIT()  asm volatile("cp.async.commit_group;\n" ::: "memory")
#define CP_WAIT(n)   asm volatile("cp.async.wait_group %0;\n" :: "n"(n) : "memory")

// ---------------------------------------------------------------------------
// transpose x[128][2048] -> xT[2048][128]
// ---------------------------------------------------------------------------
__global__ __launch_bounds__(256) void transpose_kernel(const float* __restrict__ x,
                                                        float* __restrict__ xT) {
    int idx = blockIdx.x * 256 + threadIdx.x;
    int r = idx >> 11;
    int c = idx & 2047;
    xT[c * M_ + r] = x[idx];
}

// ---------------------------------------------------------------------------
// GEMM: C[128][N] = AT^T[128][2048] @ B[2048][N] + bias, split-K (KS slices).
// ---------------------------------------------------------------------------
__global__ __launch_bounds__(256) void gemm_splitk_kernel(
    const float* __restrict__ AT, const float* __restrict__ Bw,
    const float* __restrict__ bias, float* __restrict__ Cc,
    float* __restrict__ Pp, int N, int KS)
{
    __shared__ float As[2][8][128];
    __shared__ float Bs[2][8][128];

    const int tid = threadIdx.x;
    const int tx = tid & 15;
    const int ty = tid >> 4;
    const int n0 = blockIdx.x * 128;
    const int slice = blockIdx.y;

    const int KBTOT = 256;
    const int kb0 = (slice * KBTOT) / KS;
    const int kb1 = ((slice + 1) * KBTOT) / KS;

    const int lr = tid >> 5;
    const int lc = tid & 31;
    unsigned sA = (unsigned)__cvta_generic_to_shared(&As[0][0][0]);
    unsigned sB = (unsigned)__cvta_generic_to_shared(&Bs[0][0][0]);

    u64 acc[4][8];
    #pragma unroll
    for (int p = 0; p < 4; p++)
        #pragma unroll
        for (int n = 0; n < 8; n++) acc[p][n] = 0ull;

    {
        int k = kb0 * 8 + lr;
        cp16(sA + (unsigned)(lr * 128 + lc * 4) * 4u, AT + (size_t)k * M_ + lc * 4);
        cp16(sB + (unsigned)(lr * 128 + lc * 4) * 4u, Bw + (size_t)k * N + n0 + lc * 4);
        CP_COMMIT();
    }

    for (int kb = kb0; kb < kb1; kb++) {
        int buf = (kb - kb0) & 1;
        if (kb + 1 < kb1) {
            int nb = buf ^ 1;
            int k = (kb + 1) * 8 + lr;
            cp16(sA + (unsigned)(nb * 1024 + lr * 128 + lc * 4) * 4u, AT + (size_t)k * M_ + lc * 4);
            cp16(sB + (unsigned)(nb * 1024 + lr * 128 + lc * 4) * 4u, Bw + (size_t)k * N + n0 + lc * 4);
            CP_COMMIT();
            CP_WAIT(1);
        } else {
            CP_WAIT(0);
        }
        __syncthreads();

        #pragma unroll
        for (int kk = 0; kk < 8; kk++) {
            ulonglong2 a0 = *(const ulonglong2*)&As[buf][kk][ty * 4];
            ulonglong2 a1 = *(const ulonglong2*)&As[buf][kk][64 + ty * 4];
            float4 b0 = *(const float4*)&Bs[buf][kk][tx * 4];
            float4 b1 = *(const float4*)&Bs[buf][kk][64 + tx * 4];
            u64 bd[8];
            bd[0] = dupf(b0.x); bd[1] = dupf(b0.y); bd[2] = dupf(b0.z); bd[3] = dupf(b0.w);
            bd[4] = dupf(b1.x); bd[5] = dupf(b1.y); bd[6] = dupf(b1.z); bd[7] = dupf(b1.w);
            #pragma unroll
            for (int n = 0; n < 8; n++) {
                fma2(acc[0][n], a0.x, bd[n]);
                fma2(acc[1][n], a0.y, bd[n]);
                fma2(acc[2][n], a1.x, bd[n]);
                fma2(acc[3][n], a1.y, bd[n]);
            }
        }
        __syncthreads();
    }

    float* dst = (slice == 0) ? Cc : Pp + (size_t)(slice - 1) * M_ * N;
    float4 bi0 = make_float4(0.f, 0.f, 0.f, 0.f), bi1 = bi0;
    if (slice == 0) {
        bi0 = *(const float4*)(bias + n0 + tx * 4);
        bi1 = *(const float4*)(bias + n0 + 64 + tx * 4);
    }
    #pragma unroll
    for (int p = 0; p < 4; p++) {
        int mr = (p < 2) ? (ty * 4 + 2 * p) : (64 + ty * 4 + 2 * (p - 2));
        float2 u0 = unpk(acc[p][0]), u1 = unpk(acc[p][1]), u2 = unpk(acc[p][2]), u3 = unpk(acc[p][3]);
        float2 u4 = unpk(acc[p][4]), u5 = unpk(acc[p][5]), u6 = unpk(acc[p][6]), u7 = unpk(acc[p][7]);
        float4 lo0 = make_float4(u0.x + bi0.x, u1.x + bi0.y, u2.x + bi0.z, u3.x + bi0.w);
        float4 hi0 = make_float4(u0.y + bi0.x, u1.y + bi0.y, u2.y + bi0.z, u3.y + bi0.w);
        float4 lo1 = make_float4(u4.x + bi1.x, u5.x + bi1.y, u6.x + bi1.z, u7.x + bi1.w);
        float4 hi1 = make_float4(u4.y + bi1.x, u5.y + bi1.y, u6.y + bi1.z, u7.y + bi1.w);
        *(float4*)(dst + (size_t)mr * N + n0 + tx * 4)            = lo0;
        *(float4*)(dst + (size_t)(mr + 1) * N + n0 + tx * 4)      = hi0;
        *(float4*)(dst + (size_t)mr * N + n0 + 64 + tx * 4)       = lo1;
        *(float4*)(dst + (size_t)(mr + 1) * N + n0 + 64 + tx * 4) = hi1;
    }
}

// dst[i] += sum_p parts[p][i]
__global__ __launch_bounds__(256) void addparts_kernel(float* __restrict__ dst,
                                                       const float* __restrict__ parts,
                                                       int nparts, int n4) {
    int i = blockIdx.x * 256 + threadIdx.x;
    if (i >= n4) return;
    float4 v = ((float4*)dst)[i];
    for (int p = 0; p < nparts; p++) {
        float4 a = ((const float4*)parts)[(size_t)p * n4 + i];
        v.x += a.x; v.y += a.y; v.z += a.z; v.w += a.w;
    }
    ((float4*)dst)[i] = v;
}

// ---------------------------------------------------------------------------
// Attention chunk kernel: one block per (b,h,chunk). 256 threads, 2048 blocks.
// Scores for 512 rows in smem; chunk-local softmax stats; unnormalized PV
// partial + (m,l) to global. No giant score scratch.
// ---------------------------------------------------------------------------
// smem float offsets
#define A_TILE_OFF 0                  // 2 x 64x128 = 16384
#define A_QS_OFF   16384              // 1024
#define A_SC_OFF   17408              // 512*8 = 4096
#define A_PP_OFF   21504              // 4*64*9 = 2304
#define A_RED_OFF  23808              // 160
#define A_SMEM_FLOATS 23968
#define A_SMEM_BYTES  (A_SMEM_FLOATS*4)

__device__ __forceinline__ int swiz(int r, int c) {   // 16B-chunk swizzle, 512B row
    return (c & 24) | ((c & 7) ^ (r & 7));
}

__global__ __launch_bounds__(256) void attn_chunk_kernel(
    const float* __restrict__ k_cache,
    const float* __restrict__ v_cache,
    const float* __restrict__ qkv)
{
    extern __shared__ float sm[];
    const int tid  = threadIdx.x;
    const int bx   = blockIdx.x;
    const int ch   = bx & 7;
    const int bh   = bx >> 3;
    const int b    = bh >> 4;
    const int h    = bh & 15;
    const int w    = tid >> 5;
    const int lane = tid & 31;
    const int s_chunk0 = ch * CH_;

    float* tile = sm + A_TILE_OFF;
    float* qs   = sm + A_QS_OFF;
    float* sc   = sm + A_SC_OFF;
    float* pp   = sm + A_PP_OFF;
    float* wred = sm + A_RED_OFF;         // [8 warps][8]
    float* smj  = sm + A_RED_OFF + 64;    // chunk max [8]
    float* slj  = sm + A_RED_OFF + 72;    // chunk sum [8]

    unsigned tile_s = (unsigned)__cvta_generic_to_shared(tile);

    // load q (scaled)
    const float scale = 0.08838834764831845f;
    for (int f = tid; f < T_ * D_; f += 256) {
        int j = f >> 7, d = f & 127;
        qs[f] = qkv[(size_t)(b * T_ + j) * QKV_STRIDE + h * D_ + d] * scale;
    }
    __syncthreads();

    // ---------------- scores: 8 sub-tiles of 64 K-rows ----------------
    const int r_ = tid & 63;
    const int q4 = tid >> 6;              // 0..3, quarter of d

    auto load_tile = [&](int tt, int buf) {
        int s0 = s_chunk0 + tt * 64;
        #pragma unroll
        for (int i = 0; i < 8; i++) {
            int m = tid + 256 * i;        // 2048 chunks of 16B
            int rr = m >> 5, cc = m & 31;
            int s = s0 + rr;
            const float* src = (s >= STARTPOS)
                ? qkv + (size_t)(b * T_ + (s - STARTPOS)) * QKV_STRIDE + C_ + h * D_ + cc * 4
                : k_cache + ((size_t)(b * H_ + h) * MAXSEQ + s) * (size_t)D_ + cc * 4;
            unsigned dst = tile_s + ((unsigned)buf * 2048u + (unsigned)(rr * 32 + swiz(rr, cc))) * 16u;
            cp16(dst, src);
        }
        CP_COMMIT();
    };

    load_tile(0, 0);
    for (int tt = 0; tt < 8; tt++) {
        int buf = tt & 1;
        if (tt + 1 < 8) { load_tile(tt + 1, buf ^ 1); CP_WAIT(1); }
        else            { CP_WAIT(0); }
        __syncthreads();

        u64 acc[8];
        #pragma unroll
        for (int j = 0; j < 8; j++) acc[j] = 0ull;
        const float* tb = tile + buf * 8192;
        #pragma unroll
        for (int i = 0; i < 8; i++) {
            int c = q4 * 8 + i;
            ulonglong2 kk2 = *(const ulonglong2*)(tb + (r_ * 32 + swiz(r_, c)) * 4);
            int d0 = c * 4;
            #pragma unroll
            for (int j = 0; j < 8; j++) {
                ulonglong2 q2 = *(const ulonglong2*)(qs + j * 128 + d0);
                fma2(acc[j], kk2.x, q2.x);
                fma2(acc[j], kk2.y, q2.y);
            }
        }
        #pragma unroll
        for (int j = 0; j < 8; j++) pp[(q4 * 64 + r_) * 9 + j] = hsum2(acc[j]);
        __syncthreads();

        if (tid < 64) {
            int r = tid;
            float v[8];
            #pragma unroll
            for (int j = 0; j < 8; j++)
                v[j] = pp[r * 9 + j] + pp[(64 + r) * 9 + j]
                     + pp[(128 + r) * 9 + j] + pp[(192 + r) * 9 + j];
            float* dst = sc + (tt * 64 + r) * 8;
            *(float4*)dst       = make_float4(v[0], v[1], v[2], v[3]);
            *(float4*)(dst + 4) = make_float4(v[4], v[5], v[6], v[7]);
        }
    }
    __syncthreads();

    // ---------------- chunk softmax stats (max, exp-in-place, sum) ----------
    {
        float mx[8];
        #pragma unroll
        for (int j = 0; j < 8; j++) mx[j] = -3.4e38f;
        for (int s = tid; s < CH_; s += 256) {
            float4 a = *(const float4*)(sc + s * 8);
            float4 c = *(const float4*)(sc + s * 8 + 4);
            mx[0] = fmaxf(mx[0], a.x); mx[1] = fmaxf(mx[1], a.y);
            mx[2] = fmaxf(mx[2], a.z); mx[3] = fmaxf(mx[3], a.w);
            mx[4] = fmaxf(mx[4], c.x); mx[5] = fmaxf(mx[5], c.y);
            mx[6] = fmaxf(mx[6], c.z); mx[7] = fmaxf(mx[7], c.w);
        }
        #pragma unroll
        for (int o = 16; o; o >>= 1)
            #pragma unroll
            for (int j = 0; j < 8; j++) mx[j] = fmaxf(mx[j], __shfl_xor_sync(~0u, mx[j], o));
        if (lane == 0)
            #pragma unroll
            for (int j = 0; j < 8; j++) wred[w * 8 + j] = mx[j];
    }
    __syncthreads();
    if (tid < 8) {
        float m = wred[tid];
        for (int ww = 1; ww < 8; ww++) m = fmaxf(m, wred[ww * 8 + tid]);
        smj[tid] = m;
    }
    __syncthreads();
    {
        float m[8], sum[8];
        #pragma unroll
        for (int j = 0; j < 8; j++) { m[j] = smj[j]; sum[j] = 0.f; }
        for (int s = tid; s < CH_; s += 256) {
            float4 a = *(const float4*)(sc + s * 8);
            float4 c = *(const float4*)(sc + s * 8 + 4);
            a.x = __expf(a.x - m[0]); a.y = __expf(a.y - m[1]);
            a.z = __expf(a.z - m[2]); a.w = __expf(a.w - m[3]);
            c.x = __expf(c.x - m[4]); c.y = __expf(c.y - m[5]);
            c.z = __expf(c.z - m[6]); c.w = __expf(c.w - m[7]);
            *(float4*)(sc + s * 8)     = a;
            *(float4*)(sc + s * 8 + 4) = c;
            sum[0] += a.x; sum[1] += a.y; sum[2] += a.z; sum[3] += a.w;
            sum[4] += c.x; sum[5] += c.y; sum[6] += c.z; sum[7] += c.w;
        }
        #pragma unroll
        for (int o = 16; o; o >>= 1)
            #pragma unroll
            for (int j = 0; j < 8; j++) sum[j] += __shfl_xor_sync(~0u, sum[j], o);
        if (lane == 0)
            #pragma unroll
            for (int j = 0; j < 8; j++) wred[w * 8 + j] = sum[j];
    }
    __syncthreads();
    if (tid < 8) {
        float s = 0.f;
        for (int ww = 0; ww < 8; ww++) s += wred[ww * 8 + tid];
        slj[tid] = s;
    }

    // ---------------- PV: warp w covers 64 rows, lanes across d -------------
    u64 acc[8][2];
    #pragma unroll
    for (int j = 0; j < 8; j++) { acc[j][0] = 0ull; acc[j][1] = 0ull; }
    const int db = lane * 4;
    const int lbeg = w * 64;
    for (int sl = lbeg; sl < lbeg + 64; sl += 4) {
        #pragma unroll
        for (int u = 0; u < 4; u++) {
            int local = sl + u;
            int ss = s_chunk0 + local;
            const float* vrow = (ss >= STARTPOS)
                ? qkv + (size_t)(b * T_ + (ss - STARTPOS)) * QKV_STRIDE + 2 * C_ + h * D_
                : v_cache + ((size_t)(b * H_ + h) * MAXSEQ + ss) * (size_t)D_;
            ulonglong2 vv = *(const ulonglong2*)(vrow + db);
            float4 p0 = *(const float4*)(sc + local * 8);
            float4 p1 = *(const float4*)(sc + local * 8 + 4);
            float pj[8] = {p0.x, p0.y, p0.z, p0.w, p1.x, p1.y, p1.z, p1.w};
            #pragma unroll
            for (int j = 0; j < 8; j++) {
                u64 pd = dupf(pj[j]);
                fma2(acc[j][0], vv.x, pd);
                fma2(acc[j][1], vv.y, pd);
            }
        }
    }
    __syncthreads();
    float* ypart = tile;   // reuse: [8 warps][1024]
    #pragma unroll
    for (int j = 0; j < 8; j++) {
        ulonglong2 st; st.x = acc[j][0]; st.y = acc[j][1];
        *(ulonglong2*)&ypart[w * 1024 + j * 128 + db] = st;
    }
    __syncthreads();
    for (int f = tid; f < 1024; f += 256) {
        float sum = 0.f;
        #pragma unroll
        for (int ww = 0; ww < 8; ww++) sum += ypart[ww * 1024 + f];
        g_py[(size_t)bx * 1024 + f] = sum;
    }
    if (tid < 8) {
        g_pm[bx * 8 + tid] = smj[tid];
        g_pl[bx * 8 + tid] = slj[tid];
    }
}

// ---------------------------------------------------------------------------
// Combine chunk partials per (b,h): log-sum-exp merge, write attT.
// ---------------------------------------------------------------------------
__global__ __launch_bounds__(256) void attn_reduce_kernel(float* __restrict__ attT)
{
    __shared__ float wgt[NCH][8];
    __shared__ float Lj[8];
    const int bh  = blockIdx.x;
    const int b   = bh >> 4;
    const int h   = bh & 15;
    const int tid = threadIdx.x;

    if (tid < 8) {
        int j = tid;
        float M = -3.4e38f;
        #pragma unroll
        for (int c = 0; c < NCH; c++)
            M = fmaxf(M, g_pm[(bh * NCH + c) * 8 + j]);
        float L = 0.f;
        #pragma unroll
        for (int c = 0; c < NCH; c++) {
            float wq = __expf(g_pm[(bh * NCH + c) * 8 + j] - M);
            wgt[c][j] = wq;
            L += g_pl[(bh * NCH + c) * 8 + j] * wq;
        }
        Lj[j] = L;
    }
    __syncthreads();

    for (int f = tid; f < 1024; f += 256) {
        int j = f >> 7, d = f & 127;
        float sum = 0.f;
        #pragma unroll
        for (int c = 0; c < NCH; c++)
            sum += g_py[(size_t)(bh * NCH + c) * 1024 + f] * wgt[c][j];
        attT[(size_t)(h * D_ + d) * M_ + b * T_ + j] = sum / Lj[j];
    }
}

// ---------------------------------------------------------------------------
extern "C" void kernel_launch(void* const* d_in, const int* in_sizes, int n_in,
                              void* d_out, int out_size)
{
    const float* x  = (const float*)d_in[0];
    const float* kc = (const float*)d_in[1];
    const float* vc = (const float*)d_in[2];
    const float* wa = (const float*)d_in[3];
    const float* ba = (const float*)d_in[4];
    const float* wp = (const float*)d_in[5];
    const float* bp = (const float*)d_in[6];
    float* out = (float*)d_out;

    float *xT, *qkv, *qkvp, *attT, *outp;
    cudaGetSymbolAddress((void**)&xT,   g_xT);
    cudaGetSymbolAddress((void**)&qkv,  g_qkv);
    cudaGetSymbolAddress((void**)&qkvp, g_qkvp);
    cudaGetSymbolAddress((void**)&attT, g_attT);
    cudaGetSymbolAddress((void**)&outp, g_outp);

    cudaFuncSetAttribute(attn_chunk_kernel,
                         cudaFuncAttributeMaxDynamicSharedMemorySize, A_SMEM_BYTES);

    // 1) transpose x -> xT
    transpose_kernel<<<(M_*C_)/256, 256>>>(x, xT);
    // 2) QKV GEMM, split-K 3
    gemm_splitk_kernel<<<dim3(3*C_/128, 3), 256>>>(xT, wa, ba, qkv, qkvp, 3*C_, 3);
    // 3) reduce partials into qkv
    addparts_kernel<<<(M_*3*C_/4 + 255)/256, 256>>>(qkv, qkvp, 2, M_*3*C_/4);
    // 4) attention chunks (2048 blocks) + merge
    attn_chunk_kernel<<<B_*H_*NCH, 256, A_SMEM_BYTES>>>(kc, vc, qkv);
    attn_reduce_kernel<<<B_*H_, 256>>>(attT);
    // 5) proj GEMM, split-K 9
    gemm_splitk_kernel<<<dim3(C_/128, 9), 256>>>(attT, wp, bp, out, outp, C_, 9);
    // 6) reduce partials into out
    addparts_kernel<<<(M_*C_/4 + 255)/256, 256>>>(out, outp, 8, M_*C_/4);
}

// round 8
// speedup vs baseline: 2.2153x; 1.0386x over previous
#include <cuda_runtime.h>

// Fixed problem shapes
#define B_ 16
#define T_ 8
#define C_ 2048
#define H_ 16
#define D_ 128
#define MAXSEQ 4096
#define STARTPOS 4088
#define S_ 4096
#define QKV_STRIDE (3*C_)
#define M_ (B_*T_)          // 128
#define CH_ 512             // attention s-chunk
#define NCH 8               // S_/CH_

// Scratch (static device globals: allocation-free)
__device__ float g_xT  [C_*M_];            // x transposed [2048][128]
__device__ float g_qkv [M_*3*C_];          // [128][6144]
__device__ float g_qkvp[2*M_*3*C_];        // split-K partials (2)
__device__ float g_attT[C_*M_];            // attention out transposed [2048][128]
__device__ float g_outp[8*M_*C_];          // proj split-K partials (8)
__device__ float g_py  [(size_t)B_*H_*NCH*T_*D_];  // PV partials
__device__ float g_pm  [B_*H_*NCH*T_];     // chunk maxes
__device__ float g_pl  [B_*H_*NCH*T_];     // chunk sums

typedef unsigned long long u64;

__device__ __forceinline__ u64 dupf(float x) {
    u64 r; unsigned xi = __float_as_uint(x);
    asm("mov.b64 %0, {%1, %1};" : "=l"(r) : "r"(xi));
    return r;
}
__device__ __forceinline__ void fma2(u64& d, u64 a, u64 b) {
    asm("fma.rn.f32x2 %0, %1, %2, %0;" : "+l"(d) : "l"(a), "l"(b));
}
__device__ __forceinline__ float2 unpk(u64 v) {
    unsigned lo, hi;
    asm("mov.b64 {%0, %1}, %2;" : "=r"(lo), "=r"(hi) : "l"(v));
    return make_float2(__uint_as_float(lo), __uint_as_float(hi));
}
__device__ __forceinline__ float hsum2(u64 v) { float2 f = unpk(v); return f.x + f.y; }

__device__ __forceinline__ void cp16(unsigned dst, const void* src) {
    asm volatile("cp.async.cg.shared.global [%0], [%1], 16;\n" :: "r"(dst), "l"(src));
}
#define CP_COMMIT()  asm volatile("cp.async.commit_group;\n" ::: "memory")
#define CP_WAIT(n)   asm volatile("cp.async.wait_group %0;\n" :: "n"(n) : "memory")

// ---------------------------------------------------------------------------
// transpose x[128][2048] -> xT[2048][128]
// ---------------------------------------------------------------------------
__global__ __launch_bounds__(256) void transpose_kernel(const float* __restrict__ x,
                                                        float* __restrict__ xT) {
    int idx = blockIdx.x * 256 + threadIdx.x;
    int r = idx >> 11;
    int c = idx & 2047;
    xT[c * M_ + r] = x[idx];
}

// ---------------------------------------------------------------------------
// GEMM: C[128][N] = AT^T[128][2048] @ B[2048][N] + bias, split-K (KS slices).
// ---------------------------------------------------------------------------
__global__ __launch_bounds__(256) void gemm_splitk_kernel(
    const float* __restrict__ AT, const float* __restrict__ Bw,
    const float* __restrict__ bias, float* __restrict__ Cc,
    float* __restrict__ Pp, int N, int KS)
{
    __shared__ float As[2][8][128];
    __shared__ float Bs[2][8][128];

    const int tid = threadIdx.x;
    const int tx = tid & 15;
    const int ty = tid >> 4;
    const int n0 = blockIdx.x * 128;
    const int slice = blockIdx.y;

    const int KBTOT = 256;
    const int kb0 = (slice * KBTOT) / KS;
    const int kb1 = ((slice + 1) * KBTOT) / KS;

    const int lr = tid >> 5;
    const int lc = tid & 31;
    unsigned sA = (unsigned)__cvta_generic_to_shared(&As[0][0][0]);
    unsigned sB = (unsigned)__cvta_generic_to_shared(&Bs[0][0][0]);

    u64 acc[4][8];
    #pragma unroll
    for (int p = 0; p < 4; p++)
        #pragma unroll
        for (int n = 0; n < 8; n++) acc[p][n] = 0ull;

    {
        int k = kb0 * 8 + lr;
        cp16(sA + (unsigned)(lr * 128 + lc * 4) * 4u, AT + (size_t)k * M_ + lc * 4);
        cp16(sB + (unsigned)(lr * 128 + lc * 4) * 4u, Bw + (size_t)k * N + n0 + lc * 4);
        CP_COMMIT();
    }

    for (int kb = kb0; kb < kb1; kb++) {
        int buf = (kb - kb0) & 1;
        if (kb + 1 < kb1) {
            int nb = buf ^ 1;
            int k = (kb + 1) * 8 + lr;
            cp16(sA + (unsigned)(nb * 1024 + lr * 128 + lc * 4) * 4u, AT + (size_t)k * M_ + lc * 4);
            cp16(sB + (unsigned)(nb * 1024 + lr * 128 + lc * 4) * 4u, Bw + (size_t)k * N + n0 + lc * 4);
            CP_COMMIT();
            CP_WAIT(1);
        } else {
            CP_WAIT(0);
        }
        __syncthreads();

        #pragma unroll
        for (int kk = 0; kk < 8; kk++) {
            ulonglong2 a0 = *(const ulonglong2*)&As[buf][kk][ty * 4];
            ulonglong2 a1 = *(const ulonglong2*)&As[buf][kk][64 + ty * 4];
            float4 b0 = *(const float4*)&Bs[buf][kk][tx * 4];
            float4 b1 = *(const float4*)&Bs[buf][kk][64 + tx * 4];
            u64 bd[8];
            bd[0] = dupf(b0.x); bd[1] = dupf(b0.y); bd[2] = dupf(b0.z); bd[3] = dupf(b0.w);
            bd[4] = dupf(b1.x); bd[5] = dupf(b1.y); bd[6] = dupf(b1.z); bd[7] = dupf(b1.w);
            #pragma unroll
            for (int n = 0; n < 8; n++) {
                fma2(acc[0][n], a0.x, bd[n]);
                fma2(acc[1][n], a0.y, bd[n]);
                fma2(acc[2][n], a1.x, bd[n]);
                fma2(acc[3][n], a1.y, bd[n]);
            }
        }
        __syncthreads();
    }

    float* dst = (slice == 0) ? Cc : Pp + (size_t)(slice - 1) * M_ * N;
    float4 bi0 = make_float4(0.f, 0.f, 0.f, 0.f), bi1 = bi0;
    if (slice == 0) {
        bi0 = *(const float4*)(bias + n0 + tx * 4);
        bi1 = *(const float4*)(bias + n0 + 64 + tx * 4);
    }
    #pragma unroll
    for (int p = 0; p < 4; p++) {
        int mr = (p < 2) ? (ty * 4 + 2 * p) : (64 + ty * 4 + 2 * (p - 2));
        float2 u0 = unpk(acc[p][0]), u1 = unpk(acc[p][1]), u2 = unpk(acc[p][2]), u3 = unpk(acc[p][3]);
        float2 u4 = unpk(acc[p][4]), u5 = unpk(acc[p][5]), u6 = unpk(acc[p][6]), u7 = unpk(acc[p][7]);
        float4 lo0 = make_float4(u0.x + bi0.x, u1.x + bi0.y, u2.x + bi0.z, u3.x + bi0.w);
        float4 hi0 = make_float4(u0.y + bi0.x, u1.y + bi0.y, u2.y + bi0.z, u3.y + bi0.w);
        float4 lo1 = make_float4(u4.x + bi1.x, u5.x + bi1.y, u6.x + bi1.z, u7.x + bi1.w);
        float4 hi1 = make_float4(u4.y + bi1.x, u5.y + bi1.y, u6.y + bi1.z, u7.y + bi1.w);
        *(float4*)(dst + (size_t)mr * N + n0 + tx * 4)            = lo0;
        *(float4*)(dst + (size_t)(mr + 1) * N + n0 + tx * 4)      = hi0;
        *(float4*)(dst + (size_t)mr * N + n0 + 64 + tx * 4)       = lo1;
        *(float4*)(dst + (size_t)(mr + 1) * N + n0 + 64 + tx * 4) = hi1;
    }
}

// dst[i] += sum_p parts[p][i]
__global__ __launch_bounds__(256) void addparts_kernel(float* __restrict__ dst,
                                                       const float* __restrict__ parts,
                                                       int nparts, int n4) {
    int i = blockIdx.x * 256 + threadIdx.x;
    if (i >= n4) return;
    float4 v = ((float4*)dst)[i];
    for (int p = 0; p < nparts; p++) {
        float4 a = ((const float4*)parts)[(size_t)p * n4 + i];
        v.x += a.x; v.y += a.y; v.z += a.z; v.w += a.w;
    }
    ((float4*)dst)[i] = v;
}

// ---------------------------------------------------------------------------
// Attention chunk kernel: one block per (b,h,chunk). 256 threads, 2048 blocks.
// 32-row K sub-tiles (2x16KB double buffer) for 3 CTAs/SM occupancy.
// ---------------------------------------------------------------------------
// smem float offsets
#define A_TILE_OFF 0                  // 2 x 32x128 = 8192
#define A_QS_OFF   8192               // 1024
#define A_SC_OFF   9216               // 512*8 = 4096
#define A_PP_OFF   13312              // 8*32*9 = 2304
#define A_RED_OFF  15616              // 160
#define A_SMEM_FLOATS 15776
#define A_SMEM_BYTES  (A_SMEM_FLOATS*4)

__device__ __forceinline__ int swiz(int r, int c) {   // 16B-chunk swizzle, 512B row
    return (c & 24) | ((c & 7) ^ (r & 7));
}

__global__ __launch_bounds__(256, 3) void attn_chunk_kernel(
    const float* __restrict__ k_cache,
    const float* __restrict__ v_cache,
    const float* __restrict__ qkv)
{
    extern __shared__ float sm[];
    const int tid  = threadIdx.x;
    const int bx   = blockIdx.x;
    const int ch   = bx & 7;
    const int bh   = bx >> 3;
    const int b    = bh >> 4;
    const int h    = bh & 15;
    const int w    = tid >> 5;
    const int lane = tid & 31;
    const int s_chunk0 = ch * CH_;

    float* tile = sm + A_TILE_OFF;
    float* qs   = sm + A_QS_OFF;
    float* sc   = sm + A_SC_OFF;
    float* pp   = sm + A_PP_OFF;
    float* wred = sm + A_RED_OFF;         // [8 warps][8]
    float* smj  = sm + A_RED_OFF + 64;    // chunk max [8]
    float* slj  = sm + A_RED_OFF + 72;    // chunk sum [8]

    unsigned tile_s = (unsigned)__cvta_generic_to_shared(tile);

    // load q (scaled)
    const float scale = 0.08838834764831845f;
    for (int f = tid; f < T_ * D_; f += 256) {
        int j = f >> 7, d = f & 127;
        qs[f] = qkv[(size_t)(b * T_ + j) * QKV_STRIDE + h * D_ + d] * scale;
    }
    __syncthreads();

    // ---------------- scores: 16 sub-tiles of 32 K-rows ----------------
    const int r_ = tid & 31;              // row within sub-tile
    const int e_ = tid >> 5;              // 0..7, d-eighth (16 floats)

    auto load_tile = [&](int tt, int buf) {
        int s0 = s_chunk0 + tt * 32;
        #pragma unroll
        for (int i = 0; i < 4; i++) {
            int m = tid + 256 * i;        // 1024 chunks of 16B
            int rr = m >> 5, cc = m & 31;
            int s = s0 + rr;
            const float* src = (s >= STARTPOS)
                ? qkv + (size_t)(b * T_ + (s - STARTPOS)) * QKV_STRIDE + C_ + h * D_ + cc * 4
                : k_cache + ((size_t)(b * H_ + h) * MAXSEQ + s) * (size_t)D_ + cc * 4;
            unsigned dst = tile_s + ((unsigned)buf * 1024u + (unsigned)(rr * 32 + swiz(rr, cc))) * 16u;
            cp16(dst, src);
        }
        CP_COMMIT();
    };

    load_tile(0, 0);
    for (int tt = 0; tt < 16; tt++) {
        int buf = tt & 1;
        if (tt + 1 < 16) { load_tile(tt + 1, buf ^ 1); CP_WAIT(1); }
        else             { CP_WAIT(0); }
        __syncthreads();

        u64 acc[8];
        #pragma unroll
        for (int j = 0; j < 8; j++) acc[j] = 0ull;
        const float* tb = tile + buf * 4096;
        #pragma unroll
        for (int i = 0; i < 4; i++) {
            int c = e_ * 4 + i;
            ulonglong2 kk2 = *(const ulonglong2*)(tb + (r_ * 32 + swiz(r_, c)) * 4);
            int d0 = c * 4;
            #pragma unroll
            for (int j = 0; j < 8; j++) {
                ulonglong2 q2 = *(const ulonglong2*)(qs + j * 128 + d0);
                fma2(acc[j], kk2.x, q2.x);
                fma2(acc[j], kk2.y, q2.y);
            }
        }
        #pragma unroll
        for (int j = 0; j < 8; j++) pp[(e_ * 32 + r_) * 9 + j] = hsum2(acc[j]);
        __syncthreads();

        // combine eighths: thread -> (r = tid>>3, j = tid&7)
        {
            int r = tid >> 3, j = tid & 7;
            float v = 0.f;
            #pragma unroll
            for (int ee = 0; ee < 8; ee++) v += pp[(ee * 32 + r) * 9 + j];
            sc[(tt * 32 + r) * 8 + j] = v;
        }
    }
    __syncthreads();

    // ---------------- chunk softmax stats ----------
    {
        float mx[8];
        #pragma unroll
        for (int j = 0; j < 8; j++) mx[j] = -3.4e38f;
        for (int s = tid; s < CH_; s += 256) {
            float4 a = *(const float4*)(sc + s * 8);
            float4 c = *(const float4*)(sc + s * 8 + 4);
            mx[0] = fmaxf(mx[0], a.x); mx[1] = fmaxf(mx[1], a.y);
            mx[2] = fmaxf(mx[2], a.z); mx[3] = fmaxf(mx[3], a.w);
            mx[4] = fmaxf(mx[4], c.x); mx[5] = fmaxf(mx[5], c.y);
            mx[6] = fmaxf(mx[6], c.z); mx[7] = fmaxf(mx[7], c.w);
        }
        #pragma unroll
        for (int o = 16; o; o >>= 1)
            #pragma unroll
            for (int j = 0; j < 8; j++) mx[j] = fmaxf(mx[j], __shfl_xor_sync(~0u, mx[j], o));
        if (lane == 0)
            #pragma unroll
            for (int j = 0; j < 8; j++) wred[w * 8 + j] = mx[j];
    }
    __syncthreads();
    if (tid < 8) {
        float m = wred[tid];
        for (int ww = 1; ww < 8; ww++) m = fmaxf(m, wred[ww * 8 + tid]);
        smj[tid] = m;
    }
    __syncthreads();
    {
        float m[8], sum[8];
        #pragma unroll
        for (int j = 0; j < 8; j++) { m[j] = smj[j]; sum[j] = 0.f; }
        for (int s = tid; s < CH_; s += 256) {
            float4 a = *(const float4*)(sc + s * 8);
            float4 c = *(const float4*)(sc + s * 8 + 4);
            a.x = __expf(a.x - m[0]); a.y = __expf(a.y - m[1]);
            a.z = __expf(a.z - m[2]); a.w = __expf(a.w - m[3]);
            c.x = __expf(c.x - m[4]); c.y = __expf(c.y - m[5]);
            c.z = __expf(c.z - m[6]); c.w = __expf(c.w - m[7]);
            *(float4*)(sc + s * 8)     = a;
            *(float4*)(sc + s * 8 + 4) = c;
            sum[0] += a.x; sum[1] += a.y; sum[2] += a.z; sum[3] += a.w;
            sum[4] += c.x; sum[5] += c.y; sum[6] += c.z; sum[7] += c.w;
        }
        #pragma unroll
        for (int o = 16; o; o >>= 1)
            #pragma unroll
            for (int j = 0; j < 8; j++) sum[j] += __shfl_xor_sync(~0u, sum[j], o);
        if (lane == 0)
            #pragma unroll
            for (int j = 0; j < 8; j++) wred[w * 8 + j] = sum[j];
    }
    __syncthreads();
    if (tid < 8) {
        float s = 0.f;
        for (int ww = 0; ww < 8; ww++) s += wred[ww * 8 + tid];
        slj[tid] = s;
    }

    // ---------------- PV: warp w covers 64 rows, lanes across d -------------
    u64 acc[8][2];
    #pragma unroll
    for (int j = 0; j < 8; j++) { acc[j][0] = 0ull; acc[j][1] = 0ull; }
    const int db = lane * 4;
    const int lbeg = w * 64;
    for (int sl = lbeg; sl < lbeg + 64; sl += 4) {
        #pragma unroll
        for (int u = 0; u < 4; u++) {
            int local = sl + u;
            int ss = s_chunk0 + local;
            const float* vrow = (ss >= STARTPOS)
                ? qkv + (size_t)(b * T_ + (ss - STARTPOS)) * QKV_STRIDE + 2 * C_ + h * D_
                : v_cache + ((size_t)(b * H_ + h) * MAXSEQ + ss) * (size_t)D_;
            ulonglong2 vv = *(const ulonglong2*)(vrow + db);
            float4 p0 = *(const float4*)(sc + local * 8);
            float4 p1 = *(const float4*)(sc + local * 8 + 4);
            float pj[8] = {p0.x, p0.y, p0.z, p0.w, p1.x, p1.y, p1.z, p1.w};
            #pragma unroll
            for (int j = 0; j < 8; j++) {
                u64 pd = dupf(pj[j]);
                fma2(acc[j][0], vv.x, pd);
                fma2(acc[j][1], vv.y, pd);
            }
        }
    }
    __syncthreads();
    float* ypart = tile;   // reuse: [8 warps][1024] = 8192 floats exactly
    #pragma unroll
    for (int j = 0; j < 8; j++) {
        ulonglong2 st; st.x = acc[j][0]; st.y = acc[j][1];
        *(ulonglong2*)&ypart[w * 1024 + j * 128 + db] = st;
    }
    __syncthreads();
    for (int f = tid; f < 1024; f += 256) {
        float sum = 0.f;
        #pragma unroll
        for (int ww = 0; ww < 8; ww++) sum += ypart[ww * 1024 + f];
        g_py[(size_t)bx * 1024 + f] = sum;
    }
    if (tid < 8) {
        g_pm[bx * 8 + tid] = smj[tid];
        g_pl[bx * 8 + tid] = slj[tid];
    }
}

// ---------------------------------------------------------------------------
// Combine chunk partials per (b,h): log-sum-exp merge, write attT.
// ---------------------------------------------------------------------------
__global__ __launch_bounds__(256) void attn_reduce_kernel(float* __restrict__ attT)
{
    __shared__ float wgt[NCH][8];
    __shared__ float Lj[8];
    const int bh  = blockIdx.x;
    const int b   = bh >> 4;
    const int h   = bh & 15;
    const int tid = threadIdx.x;

    if (tid < 8) {
        int j = tid;
        float M = -3.4e38f;
        #pragma unroll
        for (int c = 0; c < NCH; c++)
            M = fmaxf(M, g_pm[(bh * NCH + c) * 8 + j]);
        float L = 0.f;
        #pragma unroll
        for (int c = 0; c < NCH; c++) {
            float wq = __expf(g_pm[(bh * NCH + c) * 8 + j] - M);
            wgt[c][j] = wq;
            L += g_pl[(bh * NCH + c) * 8 + j] * wq;
        }
        Lj[j] = L;
    }
    __syncthreads();

    for (int f = tid; f < 1024; f += 256) {
        int j = f >> 7, d = f & 127;
        float sum = 0.f;
        #pragma unroll
        for (int c = 0; c < NCH; c++)
            sum += g_py[(size_t)(bh * NCH + c) * 1024 + f] * wgt[c][j];
        attT[(size_t)(h * D_ + d) * M_ + b * T_ + j] = sum / Lj[j];
    }
}

// ---------------------------------------------------------------------------
extern "C" void kernel_launch(void* const* d_in, const int* in_sizes, int n_in,
                              void* d_out, int out_size)
{
    const float* x  = (const float*)d_in[0];
    const float* kc = (const float*)d_in[1];
    const float* vc = (const float*)d_in[2];
    const float* wa = (const float*)d_in[3];
    const float* ba = (const float*)d_in[4];
    const float* wp = (const float*)d_in[5];
    const float* bp = (const float*)d_in[6];
    float* out = (float*)d_out;

    float *xT, *qkv, *qkvp, *attT, *outp;
    cudaGetSymbolAddress((void**)&xT,   g_xT);
    cudaGetSymbolAddress((void**)&qkv,  g_qkv);
    cudaGetSymbolAddress((void**)&qkvp, g_qkvp);
    cudaGetSymbolAddress((void**)&attT, g_attT);
    cudaGetSymbolAddress((void**)&outp, g_outp);

    cudaFuncSetAttribute(attn_chunk_kernel,
                         cudaFuncAttributeMaxDynamicSharedMemorySize, A_SMEM_BYTES);

    // 1) transpose x -> xT
    transpose_kernel<<<(M_*C_)/256, 256>>>(x, xT);
    // 2) QKV GEMM, split-K 3
    gemm_splitk_kernel<<<dim3(3*C_/128, 3), 256>>>(xT, wa, ba, qkv, qkvp, 3*C_, 3);
    // 3) reduce partials into qkv
    addparts_kernel<<<(M_*3*C_/4 + 255)/256, 256>>>(qkv, qkvp, 2, M_*3*C_/4);
    // 4) attention chunks (2048 blocks) + merge
    attn_chunk_kernel<<<B_*H_*NCH, 256, A_SMEM_BYTES>>>(kc, vc, qkv);
    attn_reduce_kernel<<<B_*H_, 256>>>(attT);
    // 5) proj GEMM, split-K 9
    gemm_splitk_kernel<<<dim3(C_/128, 9), 256>>>(attT, wp, bp, out, outp, C_, 9);
    // 6) reduce partials into out
    addparts_kernel<<<(M_*C_/4 + 255)/256, 256>>>(out, outp, 8, M_*C_/4);
}